// round 15
// baseline (speedup 1.0000x reference)
#include <cuda_runtime.h>
#include <cuda_fp16.h>
#include <cstdint>

#define SQ     192
#define DM     512
#define NH     8
#define DK     64

// attn smem byte offsets (sP eliminated)
#define SM_A    0        // A': 64 x 36 h2 (144B stride)            9216
#define SM_K1   9216     // k1: 192 x 36 h2                        27648
#define SM_V1   36864    // v1t: 64 x 100 h2 (400B stride)         25600
#define SM_ROW  62464    // rowsums [64][4] f32                     1024
#define SM_QSC  63488
#define SM_SOUT 63744
#define SM_DYN  64000

// projh smem: 4-stage ring, stage = X[64x144B] + W[64x144B] = 18432 B
#define PJ_STG  18432
#define PJ_DYN  73728

// finalk smem: X,W 64 rows x 144B each
#define FK_ST   144
#define FK_W    9216
#define FK_SZ   18432

// Scratch (allocation-free rule: __device__ globals)
__device__ float  g_q   [NH*SQ*DK];
__device__ float  g_k0  [NH*SQ*DK];
__device__ float  g_v0  [NH*SQ*DK];
__device__ __half g_k1h [NH*SQ*DK];   // [h][s][d]
__device__ __half g_v1t [NH*DK*SQ];   // [h][d][s]
__device__ __half g_atth[SQ*DM];      // attention output, f16
__device__ __half g_Xh  [3][SQ*DM];   // query,key,value f16
__device__ __half g_Wh  [6][DM*DM];   // Wq,Wk0,Wk1,Wv0,Wv1,Wo f16

__device__ __forceinline__ void hmma(float* c, const uint32_t* a,
                                     uint32_t b0, uint32_t b1) {
    asm volatile(
        "mma.sync.aligned.m16n8k16.row.col.f32.f16.f16.f32 "
        "{%0,%1,%2,%3}, {%4,%5,%6,%7}, {%8,%9}, {%0,%1,%2,%3};"
        : "+f"(c[0]), "+f"(c[1]), "+f"(c[2]), "+f"(c[3])
        : "r"(a[0]), "r"(a[1]), "r"(a[2]), "r"(a[3]), "r"(b0), "r"(b1));
}
__device__ __forceinline__ void ldsm4(uint32_t* r, uint32_t addr) {
    asm volatile("ldmatrix.sync.aligned.m8n8.x4.shared.b16 {%0,%1,%2,%3}, [%4];"
        : "=r"(r[0]), "=r"(r[1]), "=r"(r[2]), "=r"(r[3]) : "r"(addr));
}
__device__ __forceinline__ uint32_t s2u(const void* p) {
    uint32_t a;
    asm("{ .reg .u64 t; cvta.to.shared.u64 t, %1; cvt.u32.u64 %0, t; }"
        : "=r"(a) : "l"(p));
    return a;
}
__device__ __forceinline__ float ex2f(float x) {
    float r;
    asm("ex2.approx.f32 %0, %1;" : "=f"(r) : "f"(x));
    return r;
}
#define CP16(dst, src) \
    asm volatile("cp.async.ca.shared.global [%0], [%1], 16;" \
                 :: "r"(dst), "l"(src) : "memory")
#define CPCOMMIT() asm volatile("cp.async.commit_group;" ::: "memory")
#define CPWAIT(n)  asm volatile("cp.async.wait_group %0;" :: "n"(n) : "memory")

// ---------------------------------------------------------------------------
// Convert inputs + weights to f16; seg 9 initializes d_out with bias bo.
// ---------------------------------------------------------------------------
__global__ __launch_bounds__(256) void conv_kernel(
    const float* __restrict__ query, const float* __restrict__ keyi,
    const float* __restrict__ value,
    const float* __restrict__ Wq,  const float* __restrict__ Wk0,
    const float* __restrict__ Wk1, const float* __restrict__ Wv0,
    const float* __restrict__ Wv1, const float* __restrict__ Wo,
    const float* __restrict__ bo,  float* __restrict__ out)
{
    const int seg = blockIdx.y;
    if (seg == 9) {
        for (int i = blockIdx.x*256 + threadIdx.x; i < SQ*DM/4; i += gridDim.x*256)
            ((float4*)out)[i] = ((const float4*)bo)[i & 127];
        return;
    }
    const float* src; __half* dst; int n4;
    switch (seg) {
        case 0: src = query; dst = g_Xh[0]; n4 = SQ*DM/4; break;
        case 1: src = keyi;  dst = g_Xh[1]; n4 = SQ*DM/4; break;
        case 2: src = value; dst = g_Xh[2]; n4 = SQ*DM/4; break;
        case 3: src = Wq;    dst = g_Wh[0]; n4 = DM*DM/4; break;
        case 4: src = Wk0;   dst = g_Wh[1]; n4 = DM*DM/4; break;
        case 5: src = Wk1;   dst = g_Wh[2]; n4 = DM*DM/4; break;
        case 6: src = Wv0;   dst = g_Wh[3]; n4 = DM*DM/4; break;
        case 7: src = Wv1;   dst = g_Wh[4]; n4 = DM*DM/4; break;
        default:src = Wo;    dst = g_Wh[5]; n4 = DM*DM/4; break;
    }
    for (int i = blockIdx.x*256 + threadIdx.x; i < n4; i += gridDim.x*256) {
        float4 f = ((const float4*)src)[i];
        __half2 h0 = __floats2half2_rn(f.x, f.y);
        __half2 h1 = __floats2half2_rn(f.z, f.w);
        uint2 u; u.x = *(uint32_t*)&h0; u.y = *(uint32_t*)&h1;
        ((uint2*)dst)[i] = u;
    }
}

// ---------------------------------------------------------------------------
// f16 tensor-core projection, cp.async 4-stage pipeline (unchanged from R14).
// ---------------------------------------------------------------------------
__global__ __launch_bounds__(256) void projh_kernel(
    const float* __restrict__ bq,  const float* __restrict__ bk0,
    const float* __restrict__ bk1, const float* __restrict__ bv0,
    const float* __restrict__ bv1)
{
    extern __shared__ __align__(16) char psm[];

    const int sel = blockIdx.z;
    const __half *X, *W; const float* B;
    switch (sel) {
        case 0:  X = g_Xh[0]; W = g_Wh[0]; B = bq;  break;
        case 1:  X = g_Xh[1]; W = g_Wh[1]; B = bk0; break;
        case 2:  X = g_Xh[1]; W = g_Wh[2]; B = bk1; break;
        case 3:  X = g_Xh[2]; W = g_Wh[3]; B = bv0; break;
        default: X = g_Xh[2]; W = g_Wh[4]; B = bv1; break;
    }

    const int bs  = blockIdx.x * 64;
    const int bo_ = blockIdx.y * 64;
    const int tid = threadIdx.x;
    const int warp = tid >> 5, lane = tid & 31;
    const int grp  = lane >> 2, tig = lane & 3;
    const int lw   = warp & 1;
    const int mw   = warp >> 1;

    const uint32_t sbu = s2u(psm);
    const int er = tid >> 2, ec = tid & 3;

    #define PJ_ISSUE(ch)  do {                                              \
        int st_ = (ch) & 3;                                                  \
        uint32_t xb = sbu + st_*PJ_STG + er*144;                             \
        uint32_t wb = xb + 9216;                                             \
        const __half* xs = X + (size_t)(bs  + er)*DM + (ch)*64;              \
        const __half* ws = W + (size_t)(bo_ + er)*DM + (ch)*64;              \
        CP16(xb + ec*16,        xs + ec*8);                                  \
        CP16(xb + (ec+4)*16,    xs + (ec+4)*8);                              \
        CP16(wb + ec*16,        ws + ec*8);                                  \
        CP16(wb + (ec+4)*16,    ws + (ec+4)*8);                              \
    } while (0)

    const uint32_t abase = sbu +
        ((lane & 7) + ((lane >> 3) & 1)*8 + lw*32)*144 + (lane >> 4)*16;
    const uint32_t bbase = sbu + 9216 +
        (mw*16 + ((lane >> 4) & 1)*8 + (lane & 7))*144 + ((lane >> 3) & 1)*16;

    PJ_ISSUE(0); CPCOMMIT();
    PJ_ISSUE(1); CPCOMMIT();
    PJ_ISSUE(2); CPCOMMIT();

    float acc[2][2][4] = {};
    #pragma unroll
    for (int ch = 0; ch < 8; ch++) {
        if (ch < 5) { PJ_ISSUE(ch + 3); CPCOMMIT(); }
        if      (ch <= 4) CPWAIT(3);
        else if (ch == 5) CPWAIT(2);
        else if (ch == 6) CPWAIT(1);
        else              CPWAIT(0);
        __syncthreads();
        const uint32_t ab = abase + (ch & 3)*PJ_STG;
        const uint32_t bb = bbase + (ch & 3)*PJ_STG;
        #pragma unroll
        for (int ks = 0; ks < 4; ks++) {
            uint32_t a0[4], a1[4], bm[4];
            ldsm4(a0, ab + ks*32);
            ldsm4(a1, ab + 2304 + ks*32);
            ldsm4(bm, bb + ks*32);
            hmma(acc[0][0], a0, bm[0], bm[1]);
            hmma(acc[0][1], a0, bm[2], bm[3]);
            hmma(acc[1][0], a1, bm[0], bm[1]);
            hmma(acc[1][1], a1, bm[2], bm[3]);
        }
        __syncthreads();
    }

    #pragma unroll
    for (int i = 0; i < 2; i++) {
        #pragma unroll
        for (int j = 0; j < 2; j++) {
            int o = bo_ + mw*16 + j*8 + tig*2;
            float2 bb2 = *(const float2*)&B[o];
            #pragma unroll
            for (int half = 0; half < 2; half++) {
                int s = bs + lw*32 + i*16 + grp + half*8;
                float r0 = acc[i][j][half*2]     + bb2.x;
                float r1 = acc[i][j][half*2 + 1] + bb2.y;
                if (sel == 2) {
                    __half2* dst = (__half2*)&g_k1h[(o >> 6)*(SQ*DK) + s*DK + (o & 63)];
                    *dst = __floats2half2_rn(r0, r1);
                } else if (sel == 4) {
                    int hh = o >> 6, dd = o & 63;
                    g_v1t[hh*(DK*SQ) + dd*SQ + s]     = __float2half_rn(r0);
                    g_v1t[hh*(DK*SQ) + (dd+1)*SQ + s] = __float2half_rn(r1);
                } else {
                    float* dst = (sel == 0) ? g_q : (sel == 1) ? g_k0 : g_v0;
                    *(float2*)&dst[(o >> 6)*(SQ*DK) + s*DK + (o & 63)] =
                        make_float2(r0, r1);
                }
            }
        }
    }
}

// ---------------------------------------------------------------------------
// Final projection, split-K x8: grid (3,8,8), K=64 per CTA, atomicAdd to out.
// ---------------------------------------------------------------------------
__global__ __launch_bounds__(256) void finalk(float* __restrict__ out)
{
    __shared__ __align__(16) char fsm[FK_SZ];

    const int bs  = blockIdx.x * 64;
    const int bo_ = blockIdx.y * 64;
    const int kq  = blockIdx.z;          // K eighth: cols kq*64..+63
    const int tid = threadIdx.x;
    const int warp = tid >> 5, lane = tid & 31;
    const int grp  = lane >> 2, tig = lane & 3;
    const int lw   = warp & 1;
    const int mw   = warp >> 1;

    const uint32_t sbu = s2u(fsm);
    {
        const int r = tid >> 2, c0 = tid & 3;
        const __half* xs = g_atth  + (size_t)(bs  + r)*DM + kq*64;
        const __half* ws = g_Wh[5] + (size_t)(bo_ + r)*DM + kq*64;
        CP16(sbu + r*FK_ST + c0*16,            xs + c0*8);
        CP16(sbu + r*FK_ST + (c0+4)*16,        xs + (c0+4)*8);
        CP16(sbu + FK_W + r*FK_ST + c0*16,     ws + c0*8);
        CP16(sbu + FK_W + r*FK_ST + (c0+4)*16, ws + (c0+4)*8);
    }
    CPCOMMIT(); CPWAIT(0);
    __syncthreads();

    const uint32_t abase = sbu +
        ((lane & 7) + ((lane >> 3) & 1)*8 + lw*32)*FK_ST + (lane >> 4)*16;
    const uint32_t bbase = sbu + FK_W +
        (mw*16 + ((lane >> 4) & 1)*8 + (lane & 7))*FK_ST + ((lane >> 3) & 1)*16;

    float acc[2][2][4] = {};
    #pragma unroll
    for (int ks = 0; ks < 4; ks++) {
        uint32_t a0[4], a1[4], bm[4];
        ldsm4(a0, abase + ks*32);
        ldsm4(a1, abase + 16*FK_ST + ks*32);
        ldsm4(bm, bbase + ks*32);
        hmma(acc[0][0], a0, bm[0], bm[1]);
        hmma(acc[0][1], a0, bm[2], bm[3]);
        hmma(acc[1][0], a1, bm[0], bm[1]);
        hmma(acc[1][1], a1, bm[2], bm[3]);
    }

    #pragma unroll
    for (int i = 0; i < 2; i++) {
        #pragma unroll
        for (int j = 0; j < 2; j++) {
            int o = bo_ + mw*16 + j*8 + tig*2;
            #pragma unroll
            for (int half = 0; half < 2; half++) {
                int s = bs + lw*32 + i*16 + grp + half*8;
                atomicAdd(&out[s*DM + o],     acc[i][j][half*2]);
                atomicAdd(&out[s*DM + o + 1], acc[i][j][half*2 + 1]);
            }
        }
    }
}

// ---------------------------------------------------------------------------
// Attention core: one CTA per (h,k), 256 threads, 2 CTAs/SM.
// P held in registers (GEMM1 C-frag == GEMM2 A-frag layout); warp-split-K
// GEMM2 over m; exp via raw ex2 (log2e folded into q scale).
// ---------------------------------------------------------------------------
__global__ __launch_bounds__(256, 2)
void attn_kernel()
{
    extern __shared__ __align__(16) char smem[];
    const uint32_t sbu = s2u(smem);
    __half2* sA2  = (__half2*)(smem + SM_A);    // [64][36]
    float*   sRow = (float*)(smem + SM_ROW);    // [64][4]
    float*   qsc  = (float*)(smem + SM_QSC);
    float*   sout = (float*)(smem + SM_SOUT);

    const int k    = blockIdx.x;
    const int h    = blockIdx.y;
    const int tid  = threadIdx.x;
    const int warp = tid >> 5, lane = tid & 31;
    const int grp  = lane >> 2, tig = lane & 3;
    const int lw   = warp & 1;
    const int mw   = warp >> 1;

    const float*  qp  = g_q   + (h*SQ + k) * DK;
    const float*  k0p = g_k0  + h*SQ*DK;
    const float*  v0p = g_v0  + h*SQ*DK;
    const __half* k1h = g_k1h + h*SQ*DK;
    const __half* v1t = g_v1t + h*DK*SQ;

    if (tid < 64) { qsc[tid] = qp[tid] * (0.125f * 1.4426950408889634f); sout[tid] = 0.0f; }
    {
        const float4* ksrc = (const float4*)k1h;
        #pragma unroll
        for (int e = tid; e < 1536; e += 256) {
            int m = e >> 3, c = e & 7;
            ((float4*)(smem + SM_K1 + m*144))[c] = ksrc[m*8 + c];
        }
        const float4* vsrc = (const float4*)v1t;
        #pragma unroll
        for (int e = tid; e < 1536; e += 256) {
            int d = e / 24, c = e % 24;
            ((float4*)(smem + SM_V1 + d*400))[c] = vsrc[d*24 + c];
        }
    }
    __syncthreads();

    const uint32_t abase = sbu + SM_A +
        ((lane & 7) + ((lane >> 3) & 1)*8 + lw*32)*144 + (lane >> 4)*16;
    const uint32_t bbase = sbu + SM_K1 +
        (mw*48 + ((lane >> 4) & 1)*8 + (lane & 7))*144 + ((lane >> 3) & 1)*16;
    // GEMM2 B: all 64 d rows, warp's own m columns (mw*48..)
    const uint32_t vbase = sbu + SM_V1 +
        (((lane >> 4) & 1)*8 + (lane & 7))*400 + mw*96 + ((lane >> 3) & 1)*16;

    float pd[16] = {};   // cols jb*8 + tig*2, +1 ; summed over this thread's rows

    for (int lt = 0; lt < 3; lt++) {
        // ---- stage A': sA2[l][dp] = h2(qsc*k0), rows lt*64.. ----
        #pragma unroll
        for (int e = tid; e < 2048; e += 256) {
            int l = e >> 5, dp = e & 31;
            float2 kk = *(const float2*)&k0p[(lt*64 + l)*DK + 2*dp];
            float2 qq = *(const float2*)&qsc[2*dp];
            sA2[l*36 + dp] = __floats2half2_rn(qq.x*kk.x, qq.y*kk.y);
        }
        __syncthreads();

        // ---- GEMM1: S[64 x 192] = A' @ k1^T ----
        float c1[2][6][4] = {};
        #pragma unroll
        for (int ks = 0; ks < 4; ks++) {
            uint32_t a0[4], a1[4], bm[12];
            ldsm4(a0, abase + ks*32);
            ldsm4(a1, abase + 2304 + ks*32);
            ldsm4(&bm[0], bbase + ks*32);
            ldsm4(&bm[4], bbase + 2304 + ks*32);
            ldsm4(&bm[8], bbase + 4608 + ks*32);
            #pragma unroll
            for (int j = 0; j < 6; j++) {
                uint32_t b0 = bm[(j >> 1)*4 + (j & 1)*2];
                uint32_t b1 = bm[(j >> 1)*4 + (j & 1)*2 + 1];
                hmma(c1[0][j], a0, b0, b1);
                hmma(c1[1][j], a1, b0, b1);
            }
        }

        // ---- softmax in registers: exp2, rowsums, pack into A-fragments ----
        uint32_t pA[2][6], pB[2][6];
        float rs[2][2] = {};
        #pragma unroll
        for (int i = 0; i < 2; i++) {
            #pragma unroll
            for (int j = 0; j < 6; j++) {
                float e0 = ex2f(c1[i][j][0]);
                float e1 = ex2f(c1[i][j][1]);
                float e2 = ex2f(c1[i][j][2]);
                float e3 = ex2f(c1[i][j][3]);
                rs[i][0] += e0 + e1;
                rs[i][1] += e2 + e3;
                __half2 h01 = __floats2half2_rn(e0, e1);
                __half2 h23 = __floats2half2_rn(e2, e3);
                pA[i][j] = *(uint32_t*)&h01;
                pB[i][j] = *(uint32_t*)&h23;
            }
        }
        #pragma unroll
        for (int i = 0; i < 2; i++)
            #pragma unroll
            for (int t = 0; t < 2; t++) {
                rs[i][t] += __shfl_xor_sync(0xffffffffu, rs[i][t], 1);
                rs[i][t] += __shfl_xor_sync(0xffffffffu, rs[i][t], 2);
            }
        if (tig == 0) {
            #pragma unroll
            for (int i = 0; i < 2; i++)
                #pragma unroll
                for (int t = 0; t < 2; t++)
                    sRow[(lw*32 + i*16 + t*8 + grp)*4 + mw] = rs[i][t];
        }
        __syncthreads();

        // ---- GEMM2 (warp-split-K over m): u_part = P_frag @ v1 ----
        float c2[2][8][4] = {};
        #pragma unroll
        for (int ks = 0; ks < 3; ks++) {
            uint32_t a[2][4];
            #pragma unroll
            for (int i = 0; i < 2; i++) {
                a[i][0] = pA[i][2*ks];
                a[i][1] = pB[i][2*ks];
                a[i][2] = pA[i][2*ks + 1];
                a[i][3] = pB[i][2*ks + 1];
            }
            #pragma unroll
            for (int db = 0; db < 4; db++) {
                uint32_t bm[4];
                ldsm4(bm, vbase + db*6400 + ks*32);
                hmma(c2[0][2*db],     a[0], bm[0], bm[1]);
                hmma(c2[0][2*db + 1], a[0], bm[2], bm[3]);
                hmma(c2[1][2*db],     a[1], bm[0], bm[1]);
                hmma(c2[1][2*db + 1], a[1], bm[2], bm[3]);
            }
        }

        // ---- epilogue: pd += u_part * v0 * (1/rowsum) ----
        #pragma unroll
        for (int i = 0; i < 2; i++) {
            int rl = lw*32 + i*16 + grp;
            int r  = lt*64 + rl;
            float4 q0 = *(const float4*)&sRow[rl*4];
            float4 q1 = *(const float4*)&sRow[(rl+8)*4];
            float inv0 = __fdividef(1.0f, q0.x + q0.y + q0.z + q0.w);
            float inv1 = __fdividef(1.0f, q1.x + q1.y + q1.z + q1.w);
            #pragma unroll
            for (int jb = 0; jb < 8; jb++) {
                int dc = jb*8 + tig*2;
                float2 va = *(const float2*)&v0p[r*DK + dc];
                float2 vb = *(const float2*)&v0p[(r+8)*DK + dc];
                pd[2*jb]     += c2[i][jb][0]*va.x*inv0 + c2[i][jb][2]*vb.x*inv1;
                pd[2*jb + 1] += c2[i][jb][1]*va.y*inv0 + c2[i][jb][3]*vb.y*inv1;
            }
        }
        // no end-of-lt sync needed: next staging writes sA2 only; all warps
        // already passed their GEMM1 reads (guaranteed by the sRow sync).
    }

    // reduce pd over grp lanes (rows), then across warps via smem atomics
    #pragma unroll
    for (int t = 0; t < 16; t++) {
        pd[t] += __shfl_xor_sync(0xffffffffu, pd[t], 4);
        pd[t] += __shfl_xor_sync(0xffffffffu, pd[t], 8);
        pd[t] += __shfl_xor_sync(0xffffffffu, pd[t], 16);
    }
    if (lane < 4) {
        #pragma unroll
        for (int jb = 0; jb < 8; jb++) {
            atomicAdd(&sout[jb*8 + lane*2],     pd[2*jb]);
            atomicAdd(&sout[jb*8 + lane*2 + 1], pd[2*jb + 1]);
        }
    }
    __syncthreads();
    if (tid < 64)
        g_atth[k*DM + h*DK + tid] = __float2half_rn(sout[tid]);
}

// ---------------------------------------------------------------------------
extern "C" void kernel_launch(void* const* d_in, const int* in_sizes, int n_in,
                              void* d_out, int out_size)
{
    (void)in_sizes; (void)n_in; (void)out_size;

    const float* query = (const float*)d_in[0];
    const float* key   = (const float*)d_in[1];
    const float* value = (const float*)d_in[2];
    const float* Wq    = (const float*)d_in[3];
    const float* bq    = (const float*)d_in[4];
    const float* Wk0   = (const float*)d_in[5];
    const float* bk0   = (const float*)d_in[6];
    const float* Wk1   = (const float*)d_in[7];
    const float* bk1   = (const float*)d_in[8];
    const float* Wv0   = (const float*)d_in[9];
    const float* bv0   = (const float*)d_in[10];
    const float* Wv1   = (const float*)d_in[11];
    const float* bv1   = (const float*)d_in[12];
    const float* Wo    = (const float*)d_in[13];
    const float* bo    = (const float*)d_in[14];
    float* out = (float*)d_out;

    cudaFuncSetAttribute(attn_kernel,
                         cudaFuncAttributeMaxDynamicSharedMemorySize, SM_DYN);
    cudaFuncSetAttribute(projh_kernel,
                         cudaFuncAttributeMaxDynamicSharedMemorySize, PJ_DYN);

    conv_kernel<<<dim3(128, 10), 256>>>(query, key, value,
                                        Wq, Wk0, Wk1, Wv0, Wv1, Wo, bo, out);

    projh_kernel<<<dim3(3, 8, 5), 256, PJ_DYN>>>(bq, bk0, bk1, bv0, bv1);

    attn_kernel<<<dim3(SQ, NH), 256, SM_DYN>>>();

    finalk<<<dim3(3, 8, 8), 256>>>(out);
}

// round 16
// speedup vs baseline: 1.0193x; 1.0193x over previous
#include <cuda_runtime.h>
#include <cuda_fp16.h>
#include <cstdint>

#define SQ     192
#define DM     512
#define NH     8
#define DK     64

// attn smem byte offsets (no sP)
#define SM_A    0        // A': 64 x 36 h2 (144B stride)            9216
#define SM_K1   9216     // k1: 192 x 36 h2                        27648
#define SM_V1   36864    // v1t: 64 x 100 h2 (400B stride)         25600
#define SM_ROW  62464    // rowsums [64][4] f32                     1024
#define SM_QSC  63488
#define SM_SOUT 63744
#define SM_DYN  64000

// projh smem: 4-stage ring, stage = X[64x144B] + W[64x144B] = 18432 B
#define PJ_STG  18432
#define PJ_DYN  73728

// finalk smem (K=128 per CTA, R14-proven)
#define FK_ST   272
#define FK_W    17408
#define FK_SZ   34816

// Scratch (allocation-free rule: __device__ globals)
__device__ float  g_q   [NH*SQ*DK];
__device__ float  g_k0  [NH*SQ*DK];
__device__ float  g_v0  [NH*SQ*DK];
__device__ __half g_k1h [NH*SQ*DK];   // [h][s][d]
__device__ __half g_v1t [NH*DK*SQ];   // [h][d][s]
__device__ __half g_atth[SQ*DM];      // attention output, f16
__device__ __half g_Xh  [3][SQ*DM];   // query,key,value f16
__device__ __half g_Wh  [6][DM*DM];   // Wq,Wk0,Wk1,Wv0,Wv1,Wo f16

__device__ __forceinline__ void hmma(float* c, const uint32_t* a,
                                     uint32_t b0, uint32_t b1) {
    asm volatile(
        "mma.sync.aligned.m16n8k16.row.col.f32.f16.f16.f32 "
        "{%0,%1,%2,%3}, {%4,%5,%6,%7}, {%8,%9}, {%0,%1,%2,%3};"
        : "+f"(c[0]), "+f"(c[1]), "+f"(c[2]), "+f"(c[3])
        : "r"(a[0]), "r"(a[1]), "r"(a[2]), "r"(a[3]), "r"(b0), "r"(b1));
}
__device__ __forceinline__ void ldsm4(uint32_t* r, uint32_t addr) {
    asm volatile("ldmatrix.sync.aligned.m8n8.x4.shared.b16 {%0,%1,%2,%3}, [%4];"
        : "=r"(r[0]), "=r"(r[1]), "=r"(r[2]), "=r"(r[3]) : "r"(addr));
}
__device__ __forceinline__ uint32_t s2u(const void* p) {
    uint32_t a;
    asm("{ .reg .u64 t; cvta.to.shared.u64 t, %1; cvt.u32.u64 %0, t; }"
        : "=r"(a) : "l"(p));
    return a;
}
__device__ __forceinline__ float ex2f(float x) {
    float r;
    asm("ex2.approx.f32 %0, %1;" : "=f"(r) : "f"(x));
    return r;
}
#define CP16(dst, src) \
    asm volatile("cp.async.ca.shared.global [%0], [%1], 16;" \
                 :: "r"(dst), "l"(src) : "memory")
#define CPCOMMIT() asm volatile("cp.async.commit_group;" ::: "memory")
#define CPWAIT(n)  asm volatile("cp.async.wait_group %0;" :: "n"(n) : "memory")

// ---------------------------------------------------------------------------
// Convert inputs + weights to f16; seg 9 initializes d_out with bias bo.
// ---------------------------------------------------------------------------
__global__ __launch_bounds__(256) void conv_kernel(
    const float* __restrict__ query, const float* __restrict__ keyi,
    const float* __restrict__ value,
    const float* __restrict__ Wq,  const float* __restrict__ Wk0,
    const float* __restrict__ Wk1, const float* __restrict__ Wv0,
    const float* __restrict__ Wv1, const float* __restrict__ Wo,
    const float* __restrict__ bo,  float* __restrict__ out)
{
    const int seg = blockIdx.y;
    if (seg == 9) {
        for (int i = blockIdx.x*256 + threadIdx.x; i < SQ*DM/4; i += gridDim.x*256)
            ((float4*)out)[i] = ((const float4*)bo)[i & 127];
        return;
    }
    const float* src; __half* dst; int n4;
    switch (seg) {
        case 0: src = query; dst = g_Xh[0]; n4 = SQ*DM/4; break;
        case 1: src = keyi;  dst = g_Xh[1]; n4 = SQ*DM/4; break;
        case 2: src = value; dst = g_Xh[2]; n4 = SQ*DM/4; break;
        case 3: src = Wq;    dst = g_Wh[0]; n4 = DM*DM/4; break;
        case 4: src = Wk0;   dst = g_Wh[1]; n4 = DM*DM/4; break;
        case 5: src = Wk1;   dst = g_Wh[2]; n4 = DM*DM/4; break;
        case 6: src = Wv0;   dst = g_Wh[3]; n4 = DM*DM/4; break;
        case 7: src = Wv1;   dst = g_Wh[4]; n4 = DM*DM/4; break;
        default:src = Wo;    dst = g_Wh[5]; n4 = DM*DM/4; break;
    }
    for (int i = blockIdx.x*256 + threadIdx.x; i < n4; i += gridDim.x*256) {
        float4 f = ((const float4*)src)[i];
        __half2 h0 = __floats2half2_rn(f.x, f.y);
        __half2 h1 = __floats2half2_rn(f.z, f.w);
        uint2 u; u.x = *(uint32_t*)&h0; u.y = *(uint32_t*)&h1;
        ((uint2*)dst)[i] = u;
    }
}

// ---------------------------------------------------------------------------
// f16 tensor-core projection, cp.async 4-stage pipeline (unchanged from R14).
// ---------------------------------------------------------------------------
__global__ __launch_bounds__(256) void projh_kernel(
    const float* __restrict__ bq,  const float* __restrict__ bk0,
    const float* __restrict__ bk1, const float* __restrict__ bv0,
    const float* __restrict__ bv1)
{
    extern __shared__ __align__(16) char psm[];

    const int sel = blockIdx.z;
    const __half *X, *W; const float* B;
    switch (sel) {
        case 0:  X = g_Xh[0]; W = g_Wh[0]; B = bq;  break;
        case 1:  X = g_Xh[1]; W = g_Wh[1]; B = bk0; break;
        case 2:  X = g_Xh[1]; W = g_Wh[2]; B = bk1; break;
        case 3:  X = g_Xh[2]; W = g_Wh[3]; B = bv0; break;
        default: X = g_Xh[2]; W = g_Wh[4]; B = bv1; break;
    }

    const int bs  = blockIdx.x * 64;
    const int bo_ = blockIdx.y * 64;
    const int tid = threadIdx.x;
    const int warp = tid >> 5, lane = tid & 31;
    const int grp  = lane >> 2, tig = lane & 3;
    const int lw   = warp & 1;
    const int mw   = warp >> 1;

    const uint32_t sbu = s2u(psm);
    const int er = tid >> 2, ec = tid & 3;

    #define PJ_ISSUE(ch)  do {                                              \
        int st_ = (ch) & 3;                                                  \
        uint32_t xb = sbu + st_*PJ_STG + er*144;                             \
        uint32_t wb = xb + 9216;                                             \
        const __half* xs = X + (size_t)(bs  + er)*DM + (ch)*64;              \
        const __half* ws = W + (size_t)(bo_ + er)*DM + (ch)*64;              \
        CP16(xb + ec*16,        xs + ec*8);                                  \
        CP16(xb + (ec+4)*16,    xs + (ec+4)*8);                              \
        CP16(wb + ec*16,        ws + ec*8);                                  \
        CP16(wb + (ec+4)*16,    ws + (ec+4)*8);                              \
    } while (0)

    const uint32_t abase = sbu +
        ((lane & 7) + ((lane >> 3) & 1)*8 + lw*32)*144 + (lane >> 4)*16;
    const uint32_t bbase = sbu + 9216 +
        (mw*16 + ((lane >> 4) & 1)*8 + (lane & 7))*144 + ((lane >> 3) & 1)*16;

    PJ_ISSUE(0); CPCOMMIT();
    PJ_ISSUE(1); CPCOMMIT();
    PJ_ISSUE(2); CPCOMMIT();

    float acc[2][2][4] = {};
    #pragma unroll
    for (int ch = 0; ch < 8; ch++) {
        if (ch < 5) { PJ_ISSUE(ch + 3); CPCOMMIT(); }
        if      (ch <= 4) CPWAIT(3);
        else if (ch == 5) CPWAIT(2);
        else if (ch == 6) CPWAIT(1);
        else              CPWAIT(0);
        __syncthreads();
        const uint32_t ab = abase + (ch & 3)*PJ_STG;
        const uint32_t bb = bbase + (ch & 3)*PJ_STG;
        #pragma unroll
        for (int ks = 0; ks < 4; ks++) {
            uint32_t a0[4], a1[4], bm[4];
            ldsm4(a0, ab + ks*32);
            ldsm4(a1, ab + 2304 + ks*32);
            ldsm4(bm, bb + ks*32);
            hmma(acc[0][0], a0, bm[0], bm[1]);
            hmma(acc[0][1], a0, bm[2], bm[3]);
            hmma(acc[1][0], a1, bm[0], bm[1]);
            hmma(acc[1][1], a1, bm[2], bm[3]);
        }
        __syncthreads();
    }

    #pragma unroll
    for (int i = 0; i < 2; i++) {
        #pragma unroll
        for (int j = 0; j < 2; j++) {
            int o = bo_ + mw*16 + j*8 + tig*2;
            float2 bb2 = *(const float2*)&B[o];
            #pragma unroll
            for (int half = 0; half < 2; half++) {
                int s = bs + lw*32 + i*16 + grp + half*8;
                float r0 = acc[i][j][half*2]     + bb2.x;
                float r1 = acc[i][j][half*2 + 1] + bb2.y;
                if (sel == 2) {
                    __half2* dst = (__half2*)&g_k1h[(o >> 6)*(SQ*DK) + s*DK + (o & 63)];
                    *dst = __floats2half2_rn(r0, r1);
                } else if (sel == 4) {
                    int hh = o >> 6, dd = o & 63;
                    g_v1t[hh*(DK*SQ) + dd*SQ + s]     = __float2half_rn(r0);
                    g_v1t[hh*(DK*SQ) + (dd+1)*SQ + s] = __float2half_rn(r1);
                } else {
                    float* dst = (sel == 0) ? g_q : (sel == 1) ? g_k0 : g_v0;
                    *(float2*)&dst[(o >> 6)*(SQ*DK) + s*DK + (o & 63)] =
                        make_float2(r0, r1);
                }
            }
        }
    }
}

// ---------------------------------------------------------------------------
// Final projection, split-K x4 (R14-proven): grid (3,8,4), K=128 per CTA.
// ---------------------------------------------------------------------------
__global__ __launch_bounds__(256) void finalk(float* __restrict__ out)
{
    __shared__ __align__(16) char fsm[FK_SZ];

    const int bs  = blockIdx.x * 64;
    const int bo_ = blockIdx.y * 64;
    const int kq  = blockIdx.z;
    const int tid = threadIdx.x;
    const int warp = tid >> 5, lane = tid & 31;
    const int grp  = lane >> 2, tig = lane & 3;
    const int lw   = warp & 1;
    const int mw   = warp >> 1;

    const uint32_t sbu = s2u(fsm);
    {
        const int r = tid >> 2, c0 = tid & 3;
        const __half* xs = g_atth  + (size_t)(bs  + r)*DM + kq*128;
        const __half* ws = g_Wh[5] + (size_t)(bo_ + r)*DM + kq*128;
        #pragma unroll
        for (int u = 0; u < 4; u++) {
            int c = c0 + u*4;
            CP16(sbu + r*FK_ST + c*16,        xs + c*8);
            CP16(sbu + FK_W + r*FK_ST + c*16, ws + c*8);
        }
    }
    CPCOMMIT(); CPWAIT(0);
    __syncthreads();

    const uint32_t abase = sbu +
        ((lane & 7) + ((lane >> 3) & 1)*8 + lw*32)*FK_ST + (lane >> 4)*16;
    const uint32_t bbase = sbu + FK_W +
        (mw*16 + ((lane >> 4) & 1)*8 + (lane & 7))*FK_ST + ((lane >> 3) & 1)*16;

    float acc[2][2][4] = {};
    #pragma unroll
    for (int ks = 0; ks < 8; ks++) {
        uint32_t a0[4], a1[4], bm[4];
        ldsm4(a0, abase + ks*32);
        ldsm4(a1, abase + 16*FK_ST + ks*32);
        ldsm4(bm, bbase + ks*32);
        hmma(acc[0][0], a0, bm[0], bm[1]);
        hmma(acc[0][1], a0, bm[2], bm[3]);
        hmma(acc[1][0], a1, bm[0], bm[1]);
        hmma(acc[1][1], a1, bm[2], bm[3]);
    }

    #pragma unroll
    for (int i = 0; i < 2; i++) {
        #pragma unroll
        for (int j = 0; j < 2; j++) {
            int o = bo_ + mw*16 + j*8 + tig*2;
            #pragma unroll
            for (int half = 0; half < 2; half++) {
                int s = bs + lw*32 + i*16 + grp + half*8;
                atomicAdd(&out[s*DM + o],     acc[i][j][half*2]);
                atomicAdd(&out[s*DM + o + 1], acc[i][j][half*2 + 1]);
            }
        }
    }
}

// ---------------------------------------------------------------------------
// Attention core: one CTA per (h,k), 256 threads, 2 CTAs/SM.
// P in registers; GEMM2 warp-split-K over m, d processed in TWO HALVES to
// keep c2 at 32 regs (R15's spill fix). exp via ex2 (log2e folded into q).
// ---------------------------------------------------------------------------
__global__ __launch_bounds__(256, 2)
void attn_kernel()
{
    extern __shared__ __align__(16) char smem[];
    const uint32_t sbu = s2u(smem);
    __half2* sA2  = (__half2*)(smem + SM_A);
    float*   sRow = (float*)(smem + SM_ROW);
    float*   qsc  = (float*)(smem + SM_QSC);
    float*   sout = (float*)(smem + SM_SOUT);

    const int k    = blockIdx.x;
    const int h    = blockIdx.y;
    const int tid  = threadIdx.x;
    const int warp = tid >> 5, lane = tid & 31;
    const int grp  = lane >> 2, tig = lane & 3;
    const int lw   = warp & 1;
    const int mw   = warp >> 1;

    const float*  qp  = g_q   + (h*SQ + k) * DK;
    const float*  k0p = g_k0  + h*SQ*DK;
    const float*  v0p = g_v0  + h*SQ*DK;
    const __half* k1h = g_k1h + h*SQ*DK;
    const __half* v1t = g_v1t + h*DK*SQ;

    if (tid < 64) { qsc[tid] = qp[tid] * (0.125f * 1.4426950408889634f); sout[tid] = 0.0f; }
    {
        const float4* ksrc = (const float4*)k1h;
        #pragma unroll
        for (int e = tid; e < 1536; e += 256) {
            int m = e >> 3, c = e & 7;
            ((float4*)(smem + SM_K1 + m*144))[c] = ksrc[m*8 + c];
        }
        const float4* vsrc = (const float4*)v1t;
        #pragma unroll
        for (int e = tid; e < 1536; e += 256) {
            int d = e / 24, c = e % 24;
            ((float4*)(smem + SM_V1 + d*400))[c] = vsrc[d*24 + c];
        }
    }
    __syncthreads();

    const uint32_t abase = sbu + SM_A +
        ((lane & 7) + ((lane >> 3) & 1)*8 + lw*32)*144 + (lane >> 4)*16;
    const uint32_t bbase = sbu + SM_K1 +
        (mw*48 + ((lane >> 4) & 1)*8 + (lane & 7))*144 + ((lane >> 3) & 1)*16;
    const uint32_t vbase = sbu + SM_V1 +
        (((lane >> 4) & 1)*8 + (lane & 7))*400 + mw*96 + ((lane >> 3) & 1)*16;

    float pd[16] = {};   // d = jb*8 + tig*2, +1

    for (int lt = 0; lt < 3; lt++) {
        // ---- stage A' ----
        #pragma unroll
        for (int e = tid; e < 2048; e += 256) {
            int l = e >> 5, dp = e & 31;
            float2 kk = *(const float2*)&k0p[(lt*64 + l)*DK + 2*dp];
            float2 qq = *(const float2*)&qsc[2*dp];
            sA2[l*36 + dp] = __floats2half2_rn(qq.x*kk.x, qq.y*kk.y);
        }
        __syncthreads();

        // ---- GEMM1 ----
        float c1[2][6][4] = {};
        #pragma unroll
        for (int ks = 0; ks < 4; ks++) {
            uint32_t a0[4], a1[4], bm[12];
            ldsm4(a0, abase + ks*32);
            ldsm4(a1, abase + 2304 + ks*32);
            ldsm4(&bm[0], bbase + ks*32);
            ldsm4(&bm[4], bbase + 2304 + ks*32);
            ldsm4(&bm[8], bbase + 4608 + ks*32);
            #pragma unroll
            for (int j = 0; j < 6; j++) {
                uint32_t b0 = bm[(j >> 1)*4 + (j & 1)*2];
                uint32_t b1 = bm[(j >> 1)*4 + (j & 1)*2 + 1];
                hmma(c1[0][j], a0, b0, b1);
                hmma(c1[1][j], a1, b0, b1);
            }
        }

        // ---- softmax in registers; pack GEMM2 A-fragments ----
        uint32_t pA[2][6], pB[2][6];
        float rs[2][2] = {};
        #pragma unroll
        for (int i = 0; i < 2; i++) {
            #pragma unroll
            for (int j = 0; j < 6; j++) {
                float e0 = ex2f(c1[i][j][0]);
                float e1 = ex2f(c1[i][j][1]);
                float e2 = ex2f(c1[i][j][2]);
                float e3 = ex2f(c1[i][j][3]);
                rs[i][0] += e0 + e1;
                rs[i][1] += e2 + e3;
                __half2 h01 = __floats2half2_rn(e0, e1);
                __half2 h23 = __floats2half2_rn(e2, e3);
                pA[i][j] = *(uint32_t*)&h01;
                pB[i][j] = *(uint32_t*)&h23;
            }
        }
        #pragma unroll
        for (int i = 0; i < 2; i++)
            #pragma unroll
            for (int t = 0; t < 2; t++) {
                rs[i][t] += __shfl_xor_sync(0xffffffffu, rs[i][t], 1);
                rs[i][t] += __shfl_xor_sync(0xffffffffu, rs[i][t], 2);
            }
        if (tig == 0) {
            #pragma unroll
            for (int i = 0; i < 2; i++)
                #pragma unroll
                for (int t = 0; t < 2; t++)
                    sRow[(lw*32 + i*16 + t*8 + grp)*4 + mw] = rs[i][t];
        }
        __syncthreads();

        // per-row 1/sum (needs all 4 warps' partials)
        float inv0, inv1;
        {
            int rl = lw*32 + grp;
            float4 q0 = *(const float4*)&sRow[rl*4];
            float4 q1 = *(const float4*)&sRow[(rl+8)*4];
            inv0 = __fdividef(1.0f, q0.x + q0.y + q0.z + q0.w);
            inv1 = __fdividef(1.0f, q1.x + q1.y + q1.z + q1.w);
        }
        float inv2, inv3;
        {
            int rl = lw*32 + 16 + grp;
            float4 q0 = *(const float4*)&sRow[rl*4];
            float4 q1 = *(const float4*)&sRow[(rl+8)*4];
            inv2 = __fdividef(1.0f, q0.x + q0.y + q0.z + q0.w);
            inv3 = __fdividef(1.0f, q1.x + q1.y + q1.z + q1.w);
        }

        // ---- GEMM2 in two d-halves (c2 = 32 regs, no spills) ----
        #pragma unroll
        for (int half = 0; half < 2; half++) {
            float c2[2][4][4] = {};
            #pragma unroll
            for (int ks = 0; ks < 3; ks++) {
                uint32_t a[2][4];
                #pragma unroll
                for (int i = 0; i < 2; i++) {
                    a[i][0] = pA[i][2*ks];
                    a[i][1] = pB[i][2*ks];
                    a[i][2] = pA[i][2*ks + 1];
                    a[i][3] = pB[i][2*ks + 1];
                }
                #pragma unroll
                for (int db2 = 0; db2 < 2; db2++) {
                    uint32_t bm[4];
                    ldsm4(bm, vbase + (half*2 + db2)*6400 + ks*32);
                    hmma(c2[0][db2*2],     a[0], bm[0], bm[1]);
                    hmma(c2[0][db2*2 + 1], a[0], bm[2], bm[3]);
                    hmma(c2[1][db2*2],     a[1], bm[0], bm[1]);
                    hmma(c2[1][db2*2 + 1], a[1], bm[2], bm[3]);
                }
            }
            // fold this half into pd
            #pragma unroll
            for (int i = 0; i < 2; i++) {
                int r  = lt*64 + lw*32 + i*16 + grp;
                float iv0 = (i == 0) ? inv0 : inv2;
                float iv1 = (i == 0) ? inv1 : inv3;
                #pragma unroll
                for (int jb2 = 0; jb2 < 4; jb2++) {
                    int jb = half*4 + jb2;
                    int dc = jb*8 + tig*2;
                    float2 va = *(const float2*)&v0p[r*DK + dc];
                    float2 vb = *(const float2*)&v0p[(r+8)*DK + dc];
                    pd[2*jb]     += c2[i][jb2][0]*va.x*iv0 + c2[i][jb2][2]*vb.x*iv1;
                    pd[2*jb + 1] += c2[i][jb2][1]*va.y*iv0 + c2[i][jb2][3]*vb.y*iv1;
                }
            }
        }
    }

    // reduce pd over grp lanes, then across warps via smem atomics
    #pragma unroll
    for (int t = 0; t < 16; t++) {
        pd[t] += __shfl_xor_sync(0xffffffffu, pd[t], 4);
        pd[t] += __shfl_xor_sync(0xffffffffu, pd[t], 8);
        pd[t] += __shfl_xor_sync(0xffffffffu, pd[t], 16);
    }
    if (lane < 4) {
        #pragma unroll
        for (int jb = 0; jb < 8; jb++) {
            atomicAdd(&sout[jb*8 + lane*2],     pd[2*jb]);
            atomicAdd(&sout[jb*8 + lane*2 + 1], pd[2*jb + 1]);
        }
    }
    __syncthreads();
    if (tid < 64)
        g_atth[k*DM + h*DK + tid] = __float2half_rn(sout[tid]);
}

// ---------------------------------------------------------------------------
extern "C" void kernel_launch(void* const* d_in, const int* in_sizes, int n_in,
                              void* d_out, int out_size)
{
    (void)in_sizes; (void)n_in; (void)out_size;

    const float* query = (const float*)d_in[0];
    const float* key   = (const float*)d_in[1];
    const float* value = (const float*)d_in[2];
    const float* Wq    = (const float*)d_in[3];
    const float* bq    = (const float*)d_in[4];
    const float* Wk0   = (const float*)d_in[5];
    const float* bk0   = (const float*)d_in[6];
    const float* Wk1   = (const float*)d_in[7];
    const float* bk1   = (const float*)d_in[8];
    const float* Wv0   = (const float*)d_in[9];
    const float* bv0   = (const float*)d_in[10];
    const float* Wv1   = (const float*)d_in[11];
    const float* bv1   = (const float*)d_in[12];
    const float* Wo    = (const float*)d_in[13];
    const float* bo    = (const float*)d_in[14];
    float* out = (float*)d_out;

    cudaFuncSetAttribute(attn_kernel,
                         cudaFuncAttributeMaxDynamicSharedMemorySize, SM_DYN);
    cudaFuncSetAttribute(projh_kernel,
                         cudaFuncAttributeMaxDynamicSharedMemorySize, PJ_DYN);

    conv_kernel<<<dim3(128, 10), 256>>>(query, key, value,
                                        Wq, Wk0, Wk1, Wv0, Wv1, Wo, bo, out);

    projh_kernel<<<dim3(3, 8, 5), 256, PJ_DYN>>>(bq, bk0, bk1, bv0, bv1);

    attn_kernel<<<dim3(SQ, NH), 256, SM_DYN>>>();

    finalk<<<dim3(3, 8, 4), 256>>>(out);
}

// round 17
// speedup vs baseline: 1.2395x; 1.2160x over previous
#include <cuda_runtime.h>
#include <cuda_fp16.h>
#include <cstdint>

#define SQ     192
#define DM     512
#define NH     8
#define DK     64

// attn smem byte offsets
#define SM_P    0        // P: 64 rows x 100 h2 (400B stride)      25600
#define SM_A    25600    // A': 64 x 36 h2 (144B stride)            9216
#define SM_K1   34816    // k1: 192 x 36 h2                        27648
#define SM_V1   62464    // v1t: 64 x 100 h2                       25600
#define SM_ROW  88064    // rowsums [64][4] f32                     1024
#define SM_QSC  89088
#define SM_SOUT 89344
#define SM_DYN  89600

// projh smem: 4-stage ring, stage = X[64x144B] + W[64x144B] = 18432 B
#define PJ_STG  18432
#define PJ_DYN  73728

// finalk smem (K=128 per CTA)
#define FK_ST   272
#define FK_W    17408
#define FK_SZ   34816

// Scratch (allocation-free rule: __device__ globals)
__device__ float  g_q   [NH*SQ*DK];
__device__ float  g_k0  [NH*SQ*DK];
__device__ float  g_v0  [NH*SQ*DK];
__device__ __half g_k1h [NH*SQ*DK];   // [h][s][d]
__device__ __half g_v1t [NH*DK*SQ];   // [h][d][s]
__device__ __half g_atth[SQ*DM];      // attention output, f16
__device__ __half g_Xh  [3][SQ*DM];   // query,key,value f16
__device__ __half g_Wh  [6][DM*DM];   // Wq,Wk0,Wk1,Wv0,Wv1,Wo f16

__device__ __forceinline__ void hmma(float* c, const uint32_t* a,
                                     uint32_t b0, uint32_t b1) {
    asm volatile(
        "mma.sync.aligned.m16n8k16.row.col.f32.f16.f16.f32 "
        "{%0,%1,%2,%3}, {%4,%5,%6,%7}, {%8,%9}, {%0,%1,%2,%3};"
        : "+f"(c[0]), "+f"(c[1]), "+f"(c[2]), "+f"(c[3])
        : "r"(a[0]), "r"(a[1]), "r"(a[2]), "r"(a[3]), "r"(b0), "r"(b1));
}
__device__ __forceinline__ void ldsm4(uint32_t* r, uint32_t addr) {
    asm volatile("ldmatrix.sync.aligned.m8n8.x4.shared.b16 {%0,%1,%2,%3}, [%4];"
        : "=r"(r[0]), "=r"(r[1]), "=r"(r[2]), "=r"(r[3]) : "r"(addr));
}
__device__ __forceinline__ uint32_t s2u(const void* p) {
    uint32_t a;
    asm("{ .reg .u64 t; cvta.to.shared.u64 t, %1; cvt.u32.u64 %0, t; }"
        : "=r"(a) : "l"(p));
    return a;
}
__device__ __forceinline__ float ex2f(float x) {
    float r;
    asm("ex2.approx.f32 %0, %1;" : "=f"(r) : "f"(x));
    return r;
}
#define CP16(dst, src) \
    asm volatile("cp.async.ca.shared.global [%0], [%1], 16;" \
                 :: "r"(dst), "l"(src) : "memory")
#define CPCOMMIT() asm volatile("cp.async.commit_group;" ::: "memory")
#define CPWAIT(n)  asm volatile("cp.async.wait_group %0;" :: "n"(n) : "memory")

// ---------------------------------------------------------------------------
// Convert inputs + weights to f16; seg 9 initializes d_out with bias bo.
// ---------------------------------------------------------------------------
__global__ __launch_bounds__(256) void conv_kernel(
    const float* __restrict__ query, const float* __restrict__ keyi,
    const float* __restrict__ value,
    const float* __restrict__ Wq,  const float* __restrict__ Wk0,
    const float* __restrict__ Wk1, const float* __restrict__ Wv0,
    const float* __restrict__ Wv1, const float* __restrict__ Wo,
    const float* __restrict__ bo,  float* __restrict__ out)
{
    const int seg = blockIdx.y;
    if (seg == 9) {
        for (int i = blockIdx.x*256 + threadIdx.x; i < SQ*DM/4; i += gridDim.x*256)
            ((float4*)out)[i] = ((const float4*)bo)[i & 127];
        return;
    }
    const float* src; __half* dst; int n4;
    switch (seg) {
        case 0: src = query; dst = g_Xh[0]; n4 = SQ*DM/4; break;
        case 1: src = keyi;  dst = g_Xh[1]; n4 = SQ*DM/4; break;
        case 2: src = value; dst = g_Xh[2]; n4 = SQ*DM/4; break;
        case 3: src = Wq;    dst = g_Wh[0]; n4 = DM*DM/4; break;
        case 4: src = Wk0;   dst = g_Wh[1]; n4 = DM*DM/4; break;
        case 5: src = Wk1;   dst = g_Wh[2]; n4 = DM*DM/4; break;
        case 6: src = Wv0;   dst = g_Wh[3]; n4 = DM*DM/4; break;
        case 7: src = Wv1;   dst = g_Wh[4]; n4 = DM*DM/4; break;
        default:src = Wo;    dst = g_Wh[5]; n4 = DM*DM/4; break;
    }
    for (int i = blockIdx.x*256 + threadIdx.x; i < n4; i += gridDim.x*256) {
        float4 f = ((const float4*)src)[i];
        __half2 h0 = __floats2half2_rn(f.x, f.y);
        __half2 h1 = __floats2half2_rn(f.z, f.w);
        uint2 u; u.x = *(uint32_t*)&h0; u.y = *(uint32_t*)&h1;
        ((uint2*)dst)[i] = u;
    }
}

// ---------------------------------------------------------------------------
// f16 tensor-core projection, cp.async 4-stage pipeline.
// sel: 0=q 1=k0 2=k1(f16) 3=v0 4=v1(f16 transposed)
// ---------------------------------------------------------------------------
__global__ __launch_bounds__(256) void projh_kernel(
    const float* __restrict__ bq,  const float* __restrict__ bk0,
    const float* __restrict__ bk1, const float* __restrict__ bv0,
    const float* __restrict__ bv1)
{
    extern __shared__ __align__(16) char psm[];

    const int sel = blockIdx.z;
    const __half *X, *W; const float* B;
    switch (sel) {
        case 0:  X = g_Xh[0]; W = g_Wh[0]; B = bq;  break;
        case 1:  X = g_Xh[1]; W = g_Wh[1]; B = bk0; break;
        case 2:  X = g_Xh[1]; W = g_Wh[2]; B = bk1; break;
        case 3:  X = g_Xh[2]; W = g_Wh[3]; B = bv0; break;
        default: X = g_Xh[2]; W = g_Wh[4]; B = bv1; break;
    }

    const int bs  = blockIdx.x * 64;
    const int bo_ = blockIdx.y * 64;
    const int tid = threadIdx.x;
    const int warp = tid >> 5, lane = tid & 31;
    const int grp  = lane >> 2, tig = lane & 3;
    const int lw   = warp & 1;
    const int mw   = warp >> 1;

    const uint32_t sbu = s2u(psm);
    const int er = tid >> 2, ec = tid & 3;

    #define PJ_ISSUE(ch)  do {                                              \
        int st_ = (ch) & 3;                                                  \
        uint32_t xb = sbu + st_*PJ_STG + er*144;                             \
        uint32_t wb = xb + 9216;                                             \
        const __half* xs = X + (size_t)(bs  + er)*DM + (ch)*64;              \
        const __half* ws = W + (size_t)(bo_ + er)*DM + (ch)*64;              \
        CP16(xb + ec*16,        xs + ec*8);                                  \
        CP16(xb + (ec+4)*16,    xs + (ec+4)*8);                              \
        CP16(wb + ec*16,        ws + ec*8);                                  \
        CP16(wb + (ec+4)*16,    ws + (ec+4)*8);                              \
    } while (0)

    const uint32_t abase = sbu +
        ((lane & 7) + ((lane >> 3) & 1)*8 + lw*32)*144 + (lane >> 4)*16;
    const uint32_t bbase = sbu + 9216 +
        (mw*16 + ((lane >> 4) & 1)*8 + (lane & 7))*144 + ((lane >> 3) & 1)*16;

    PJ_ISSUE(0); CPCOMMIT();
    PJ_ISSUE(1); CPCOMMIT();
    PJ_ISSUE(2); CPCOMMIT();

    float acc[2][2][4] = {};
    #pragma unroll
    for (int ch = 0; ch < 8; ch++) {
        if (ch < 5) { PJ_ISSUE(ch + 3); CPCOMMIT(); }
        if      (ch <= 4) CPWAIT(3);
        else if (ch == 5) CPWAIT(2);
        else if (ch == 6) CPWAIT(1);
        else              CPWAIT(0);
        __syncthreads();
        const uint32_t ab = abase + (ch & 3)*PJ_STG;
        const uint32_t bb = bbase + (ch & 3)*PJ_STG;
        #pragma unroll
        for (int ks = 0; ks < 4; ks++) {
            uint32_t a0[4], a1[4], bm[4];
            ldsm4(a0, ab + ks*32);
            ldsm4(a1, ab + 2304 + ks*32);
            ldsm4(bm, bb + ks*32);
            hmma(acc[0][0], a0, bm[0], bm[1]);
            hmma(acc[0][1], a0, bm[2], bm[3]);
            hmma(acc[1][0], a1, bm[0], bm[1]);
            hmma(acc[1][1], a1, bm[2], bm[3]);
        }
        __syncthreads();
    }

    #pragma unroll
    for (int i = 0; i < 2; i++) {
        #pragma unroll
        for (int j = 0; j < 2; j++) {
            int o = bo_ + mw*16 + j*8 + tig*2;
            float2 bb2 = *(const float2*)&B[o];
            #pragma unroll
            for (int half = 0; half < 2; half++) {
                int s = bs + lw*32 + i*16 + grp + half*8;
                float r0 = acc[i][j][half*2]     + bb2.x;
                float r1 = acc[i][j][half*2 + 1] + bb2.y;
                if (sel == 2) {
                    __half2* dst = (__half2*)&g_k1h[(o >> 6)*(SQ*DK) + s*DK + (o & 63)];
                    *dst = __floats2half2_rn(r0, r1);
                } else if (sel == 4) {
                    int hh = o >> 6, dd = o & 63;
                    g_v1t[hh*(DK*SQ) + dd*SQ + s]     = __float2half_rn(r0);
                    g_v1t[hh*(DK*SQ) + (dd+1)*SQ + s] = __float2half_rn(r1);
                } else {
                    float* dst = (sel == 0) ? g_q : (sel == 1) ? g_k0 : g_v0;
                    *(float2*)&dst[(o >> 6)*(SQ*DK) + s*DK + (o & 63)] =
                        make_float2(r0, r1);
                }
            }
        }
    }
}

// ---------------------------------------------------------------------------
// Final projection, split-K x4: grid (3,8,4), K=128 per CTA, atomicAdd to out.
// ---------------------------------------------------------------------------
__global__ __launch_bounds__(256) void finalk(float* __restrict__ out)
{
    __shared__ __align__(16) char fsm[FK_SZ];

    const int bs  = blockIdx.x * 64;
    const int bo_ = blockIdx.y * 64;
    const int kq  = blockIdx.z;
    const int tid = threadIdx.x;
    const int warp = tid >> 5, lane = tid & 31;
    const int grp  = lane >> 2, tig = lane & 3;
    const int lw   = warp & 1;
    const int mw   = warp >> 1;

    const uint32_t sbu = s2u(fsm);
    {
        const int r = tid >> 2, c0 = tid & 3;
        const __half* xs = g_atth  + (size_t)(bs  + r)*DM + kq*128;
        const __half* ws = g_Wh[5] + (size_t)(bo_ + r)*DM + kq*128;
        #pragma unroll
        for (int u = 0; u < 4; u++) {
            int c = c0 + u*4;
            CP16(sbu + r*FK_ST + c*16,        xs + c*8);
            CP16(sbu + FK_W + r*FK_ST + c*16, ws + c*8);
        }
    }
    CPCOMMIT(); CPWAIT(0);
    __syncthreads();

    const uint32_t abase = sbu +
        ((lane & 7) + ((lane >> 3) & 1)*8 + lw*32)*FK_ST + (lane >> 4)*16;
    const uint32_t bbase = sbu + FK_W +
        (mw*16 + ((lane >> 4) & 1)*8 + (lane & 7))*FK_ST + ((lane >> 3) & 1)*16;

    float acc[2][2][4] = {};
    #pragma unroll
    for (int ks = 0; ks < 8; ks++) {
        uint32_t a0[4], a1[4], bm[4];
        ldsm4(a0, abase + ks*32);
        ldsm4(a1, abase + 16*FK_ST + ks*32);
        ldsm4(bm, bbase + ks*32);
        hmma(acc[0][0], a0, bm[0], bm[1]);
        hmma(acc[0][1], a0, bm[2], bm[3]);
        hmma(acc[1][0], a1, bm[0], bm[1]);
        hmma(acc[1][1], a1, bm[2], bm[3]);
    }

    #pragma unroll
    for (int i = 0; i < 2; i++) {
        #pragma unroll
        for (int j = 0; j < 2; j++) {
            int o = bo_ + mw*16 + j*8 + tig*2;
            #pragma unroll
            for (int half = 0; half < 2; half++) {
                int s = bs + lw*32 + i*16 + grp + half*8;
                atomicAdd(&out[s*DM + o],     acc[i][j][half*2]);
                atomicAdd(&out[s*DM + o + 1], acc[i][j][half*2 + 1]);
            }
        }
    }
}

// ---------------------------------------------------------------------------
// Attention core (R14 structure, proven 94.6us): one CTA per (h,k), 256 thr,
// 2 CTAs/SM, ldmatrix + register softmax (ex2, unnormalized P, inv folded
// into the v0 epilogue), f16 output to g_atth.
// ---------------------------------------------------------------------------
__global__ __launch_bounds__(256, 2)
void attn_kernel()
{
    extern __shared__ __align__(16) char smem[];
    const uint32_t sbu = s2u(smem);
    __half2* sP   = (__half2*)(smem + SM_P);
    __half2* sA2  = (__half2*)(smem + SM_A);
    float*   sRow = (float*)(smem + SM_ROW);
    float*   qsc  = (float*)(smem + SM_QSC);
    float*   sout = (float*)(smem + SM_SOUT);

    const int k    = blockIdx.x;
    const int h    = blockIdx.y;
    const int tid  = threadIdx.x;
    const int warp = tid >> 5, lane = tid & 31;
    const int grp  = lane >> 2, tig = lane & 3;
    const int lw   = warp & 1;
    const int mw   = warp >> 1;

    const float*  qp  = g_q   + (h*SQ + k) * DK;
    const float*  k0p = g_k0  + h*SQ*DK;
    const float*  v0p = g_v0  + h*SQ*DK;
    const __half* k1h = g_k1h + h*SQ*DK;
    const __half* v1t = g_v1t + h*DK*SQ;

    if (tid < 64) { qsc[tid] = qp[tid] * (0.125f * 1.4426950408889634f); sout[tid] = 0.0f; }
    {
        const float4* ksrc = (const float4*)k1h;
        #pragma unroll
        for (int e = tid; e < 1536; e += 256) {
            int m = e >> 3, c = e & 7;
            ((float4*)(smem + SM_K1 + m*144))[c] = ksrc[m*8 + c];
        }
        const float4* vsrc = (const float4*)v1t;
        #pragma unroll
        for (int e = tid; e < 1536; e += 256) {
            int d = e / 24, c = e % 24;
            ((float4*)(smem + SM_V1 + d*400))[c] = vsrc[d*24 + c];
        }
    }
    __syncthreads();

    const uint32_t abase = sbu + SM_A +
        ((lane & 7) + ((lane >> 3) & 1)*8 + lw*32)*144 + (lane >> 4)*16;
    const uint32_t bbase = sbu + SM_K1 +
        (mw*48 + ((lane >> 4) & 1)*8 + (lane & 7))*144 + ((lane >> 3) & 1)*16;
    const uint32_t pbase = sbu + SM_P +
        ((lane & 7) + ((lane >> 3) & 1)*8 + lw*32)*400 + (lane >> 4)*16;
    const uint32_t vbase = sbu + SM_V1 +
        (mw*16 + ((lane >> 4) & 1)*8 + (lane & 7))*400 + ((lane >> 3) & 1)*16;

    float part4[4] = {};

    for (int lt = 0; lt < 3; lt++) {
        #pragma unroll
        for (int e = tid; e < 2048; e += 256) {
            int l = e >> 5, dp = e & 31;
            float2 kk = *(const float2*)&k0p[(lt*64 + l)*DK + 2*dp];
            float2 qq = *(const float2*)&qsc[2*dp];
            sA2[l*36 + dp] = __floats2half2_rn(qq.x*kk.x, qq.y*kk.y);
        }
        __syncthreads();

        float c1[2][6][4] = {};
        #pragma unroll
        for (int ks = 0; ks < 4; ks++) {
            uint32_t a0[4], a1[4], bm[12];
            ldsm4(a0, abase + ks*32);
            ldsm4(a1, abase + 2304 + ks*32);
            ldsm4(&bm[0], bbase + ks*32);
            ldsm4(&bm[4], bbase + 2304 + ks*32);
            ldsm4(&bm[8], bbase + 4608 + ks*32);
            #pragma unroll
            for (int j = 0; j < 6; j++) {
                uint32_t b0 = bm[(j >> 1)*4 + (j & 1)*2];
                uint32_t b1 = bm[(j >> 1)*4 + (j & 1)*2 + 1];
                hmma(c1[0][j], a0, b0, b1);
                hmma(c1[1][j], a1, b0, b1);
            }
        }

        float rs[2][2] = {};
        #pragma unroll
        for (int i = 0; i < 2; i++) {
            int r = lw*32 + i*16 + grp;
            #pragma unroll
            for (int j = 0; j < 6; j++) {
                float e0 = ex2f(c1[i][j][0]);
                float e1 = ex2f(c1[i][j][1]);
                float e2 = ex2f(c1[i][j][2]);
                float e3 = ex2f(c1[i][j][3]);
                rs[i][0] += e0 + e1;
                rs[i][1] += e2 + e3;
                int mc = mw*24 + j*4 + tig;
                sP[r*100 + mc]     = __floats2half2_rn(e0, e1);
                sP[(r+8)*100 + mc] = __floats2half2_rn(e2, e3);
            }
        }
        #pragma unroll
        for (int i = 0; i < 2; i++)
            #pragma unroll
            for (int t = 0; t < 2; t++) {
                rs[i][t] += __shfl_xor_sync(0xffffffffu, rs[i][t], 1);
                rs[i][t] += __shfl_xor_sync(0xffffffffu, rs[i][t], 2);
            }
        if (tig == 0) {
            #pragma unroll
            for (int i = 0; i < 2; i++)
                #pragma unroll
                for (int t = 0; t < 2; t++)
                    sRow[(lw*32 + i*16 + t*8 + grp)*4 + mw] = rs[i][t];
        }
        __syncthreads();

        float c2[2][2][4] = {};
        #pragma unroll
        for (int ks = 0; ks < 12; ks++) {
            uint32_t a0[4], a1[4], bm[4];
            ldsm4(a0, pbase + ks*32);
            ldsm4(a1, pbase + 6400 + ks*32);
            ldsm4(bm, vbase + ks*32);
            hmma(c2[0][0], a0, bm[0], bm[1]);
            hmma(c2[0][1], a0, bm[2], bm[3]);
            hmma(c2[1][0], a1, bm[0], bm[1]);
            hmma(c2[1][1], a1, bm[2], bm[3]);
        }

        #pragma unroll
        for (int i = 0; i < 2; i++) {
            int rl = lw*32 + i*16 + grp;
            int r  = lt*64 + rl;
            float4 q0 = *(const float4*)&sRow[rl*4];
            float4 q1 = *(const float4*)&sRow[(rl+8)*4];
            float inv0 = __fdividef(1.0f, q0.x + q0.y + q0.z + q0.w);
            float inv1 = __fdividef(1.0f, q1.x + q1.y + q1.z + q1.w);
            #pragma unroll
            for (int j = 0; j < 2; j++) {
                int dc = mw*16 + j*8 + tig*2;
                float2 va = *(const float2*)&v0p[r*DK + dc];
                float2 vb = *(const float2*)&v0p[(r+8)*DK + dc];
                part4[j*2+0] += c2[i][j][0]*va.x*inv0 + c2[i][j][2]*vb.x*inv1;
                part4[j*2+1] += c2[i][j][1]*va.y*inv0 + c2[i][j][3]*vb.y*inv1;
            }
        }
        __syncthreads();
    }

    #pragma unroll
    for (int t = 0; t < 4; t++) {
        part4[t] += __shfl_xor_sync(0xffffffffu, part4[t], 4);
        part4[t] += __shfl_xor_sync(0xffffffffu, part4[t], 8);
        part4[t] += __shfl_xor_sync(0xffffffffu, part4[t], 16);
    }
    if (lane < 4) {
        #pragma unroll
        for (int t = 0; t < 4; t++)
            atomicAdd(&sout[mw*16 + (t>>1)*8 + tig*2 + (t&1)], part4[t]);
    }
    __syncthreads();
    if (tid < 64)
        g_atth[k*DM + h*DK + tid] = __float2half_rn(sout[tid]);
}

// ---------------------------------------------------------------------------
extern "C" void kernel_launch(void* const* d_in, const int* in_sizes, int n_in,
                              void* d_out, int out_size)
{
    (void)in_sizes; (void)n_in; (void)out_size;

    const float* query = (const float*)d_in[0];
    const float* key   = (const float*)d_in[1];
    const float* value = (const float*)d_in[2];
    const float* Wq    = (const float*)d_in[3];
    const float* bq    = (const float*)d_in[4];
    const float* Wk0   = (const float*)d_in[5];
    const float* bk0   = (const float*)d_in[6];
    const float* Wk1   = (const float*)d_in[7];
    const float* bk1   = (const float*)d_in[8];
    const float* Wv0   = (const float*)d_in[9];
    const float* bv0   = (const float*)d_in[10];
    const float* Wv1   = (const float*)d_in[11];
    const float* bv1   = (const float*)d_in[12];
    const float* Wo    = (const float*)d_in[13];
    const float* bo    = (const float*)d_in[14];
    float* out = (float*)d_out;

    cudaFuncSetAttribute(attn_kernel,
                         cudaFuncAttributeMaxDynamicSharedMemorySize, SM_DYN);
    cudaFuncSetAttribute(projh_kernel,
                         cudaFuncAttributeMaxDynamicSharedMemorySize, PJ_DYN);

    conv_kernel<<<dim3(128, 10), 256>>>(query, key, value,
                                        Wq, Wk0, Wk1, Wv0, Wv1, Wo, bo, out);

    projh_kernel<<<dim3(3, 8, 5), 256, PJ_DYN>>>(bq, bk0, bk1, bv0, bv1);

    attn_kernel<<<dim3(SQ, NH), 256, SM_DYN>>>();

    finalk<<<dim3(3, 8, 4), 256>>>(out);
}